// round 9
// baseline (speedup 1.0000x reference)
#include <cuda_runtime.h>
#include <cuda_fp16.h>
#include <cstdint>

#define N_NODES 50000
#define D 512
#define N_EDGES 400000
#define KTOT 1024
#define XBLKS 25000          // xconv blocks: 50000*128 vec4 / 256
#define NSCAN_BLKS 196       // ceil(50000/256)

// ---------------- scratch (device globals: allocation-free) ----------------
__device__ __align__(16) int   g_deg[N_NODES];
__device__ __align__(16) int   g_off[N_NODES];
__device__ __align__(16) int   g_cursor[N_NODES];
__device__ __align__(16) int   g_bsum[256];
__device__ __align__(16) int   g_csr[N_EDGES];
__device__ __align__(16) float g_bc[D];
__device__ __align__(16) __half g_A[(size_t)N_NODES * KTOT];      // [x | -mean]
__device__ __align__(16) __half g_Bt[(size_t)D * KTOT];           // Bt[n][k]

// ---------------- asm helpers ----------------
__device__ __forceinline__ uint32_t smem_u32(const void* p) {
    uint32_t a;
    asm("{ .reg .u64 t; cvta.to.shared.u64 t, %1; cvt.u32.u64 %0, t; }" : "=r"(a) : "l"(p));
    return a;
}
__device__ __forceinline__ void cp_async16(uint32_t dst, const void* src, int sz) {
    asm volatile("cp.async.cg.shared.global [%0], [%1], 16, %2;"
                 :: "r"(dst), "l"(src), "r"(sz) : "memory");
}
#define CP_COMMIT() asm volatile("cp.async.commit_group;" ::: "memory")
#define CP_WAIT3()  asm volatile("cp.async.wait_group 3;" ::: "memory")

__device__ __forceinline__ void ldm_x4(uint32_t* d, uint32_t addr) {
    asm volatile("ldmatrix.sync.aligned.m8n8.x4.shared.b16 {%0,%1,%2,%3}, [%4];"
                 : "=r"(d[0]), "=r"(d[1]), "=r"(d[2]), "=r"(d[3]) : "r"(addr));
}
__device__ __forceinline__ void mma_f16(float* c, const uint32_t* a, const uint32_t* b) {
    asm volatile("mma.sync.aligned.m16n8k16.row.col.f32.f16.f16.f32 "
                 "{%0,%1,%2,%3}, {%4,%5,%6,%7}, {%8,%9}, {%0,%1,%2,%3};"
                 : "+f"(c[0]), "+f"(c[1]), "+f"(c[2]), "+f"(c[3])
                 : "r"(a[0]), "r"(a[1]), "r"(a[2]), "r"(a[3]), "r"(b[0]), "r"(b[1]));
}

// ---------------- xconv: g_A[:,0:512] = fp16(x) ----------------
__global__ void xconv_kernel(const float* __restrict__ x) {
    int idx = blockIdx.x * 256 + threadIdx.x;
    int row = idx >> 7;
    int c4  = (idx & 127) * 4;
    float4 v = *reinterpret_cast<const float4*>(x + (size_t)row * D + c4);
    __half2 h0 = __floats2half2_rn(v.x, v.y);
    __half2 h1 = __floats2half2_rn(v.z, v.w);
    uint2 w = make_uint2(*reinterpret_cast<uint32_t*>(&h0), *reinterpret_cast<uint32_t*>(&h1));
    *reinterpret_cast<uint2*>(g_A + (size_t)row * KTOT + c4) = w;
}

// ---------------- hist ----------------
__global__ void hist_kernel(const int* __restrict__ dst) {
    int e = blockIdx.x * blockDim.x + threadIdx.x;
    if (e < N_EDGES) atomicAdd(&g_deg[dst[e]], 1);
}

// ---------------- multi-block exclusive scan ----------------
__global__ void scan1_kernel() {
    __shared__ int s[256];
    int t = threadIdx.x;
    int i = blockIdx.x * 256 + t;
    int v = (i < N_NODES) ? g_deg[i] : 0;
    s[t] = v;
    __syncthreads();
#pragma unroll
    for (int o = 1; o < 256; o <<= 1) {
        int tv = (t >= o) ? s[t - o] : 0;
        __syncthreads();
        s[t] += tv;
        __syncthreads();
    }
    if (i < N_NODES) g_off[i] = s[t] - v;
    if (t == 255) g_bsum[blockIdx.x] = s[255];
}
__global__ void scan2_kernel() {
    __shared__ int s[256];
    int t = threadIdx.x;
    int v = (t < NSCAN_BLKS) ? g_bsum[t] : 0;
    s[t] = v;
    __syncthreads();
#pragma unroll
    for (int o = 1; o < 256; o <<= 1) {
        int tv = (t >= o) ? s[t - o] : 0;
        __syncthreads();
        s[t] += tv;
        __syncthreads();
    }
    if (t < NSCAN_BLKS) g_bsum[t] = s[t] - v;
}
__global__ void scan3_kernel() {
    int t = threadIdx.x;
    int i = blockIdx.x * 256 + t;
    if (i < N_NODES) g_off[i] += g_bsum[blockIdx.x];
}

// ---------------- fill CSR ----------------
__global__ void fill_kernel(const int* __restrict__ src, const int* __restrict__ dst) {
    int e = blockIdx.x * blockDim.x + threadIdx.x;
    if (e >= N_EDGES) return;
    int d = dst[e];
    int p = g_off[d] + atomicAdd(&g_cursor[d], 1);
    g_csr[p] = src[e];
}

// ---------------- aggregate: g_A[:,512:1024] = fp16(-mean) -----------------
__global__ __launch_bounds__(128)
void agg_kernel() {
    int node = blockIdx.x;
    int t = threadIdx.x;
    int off = g_off[node];
    int deg = g_deg[node];

    float ax = 0.f, ay = 0.f, az = 0.f, aw = 0.f;
    for (int e = 0; e < deg; e++) {
        int s = g_csr[off + e];
        uint2 w = *reinterpret_cast<const uint2*>(g_A + (size_t)s * KTOT + t * 4);
        float2 f0 = __half22float2(*reinterpret_cast<__half2*>(&w.x));
        float2 f1 = __half22float2(*reinterpret_cast<__half2*>(&w.y));
        ax += f0.x; ay += f0.y; az += f1.x; aw += f1.y;
    }
    float sc = (deg > 0) ? (-1.0f / (float)deg) : 0.f;
    __half2 m0 = __floats2half2_rn(ax * sc, ay * sc);
    __half2 m1 = __floats2half2_rn(az * sc, aw * sc);
    uint2 w = make_uint2(*reinterpret_cast<uint32_t*>(&m0), *reinterpret_cast<uint32_t*>(&m1));
    *reinterpret_cast<uint2*>(g_A + (size_t)node * KTOT + D + t * 4) = w;
}

// ---------------- bprep (+ bias): g_Bt = fp16(T([[W1+W2],[W2]])) -----------
__global__ void bprep_kernel(const float* __restrict__ W1, const float* __restrict__ W2,
                             const float* __restrict__ b1, const float* __restrict__ b2) {
    __shared__ float tile[32][33];
    if (blockIdx.x == 0 && blockIdx.y == 0) {
        int ft = threadIdx.y * 32 + threadIdx.x;
        if (ft < D) g_bc[ft] = b1[ft] + b2[ft];
    }
    int k0 = blockIdx.x * 32, n0 = blockIdx.y * 32;
    int kk = k0 + threadIdx.y, nn = n0 + threadIdx.x;
    float v = (kk < D) ? (W1[kk * D + nn] + W2[kk * D + nn]) : W2[(kk - D) * D + nn];
    tile[threadIdx.y][threadIdx.x] = v;
    __syncthreads();
    int wn = n0 + threadIdx.y, wk = k0 + threadIdx.x;
    g_Bt[(size_t)wn * KTOT + wk] = __float2half_rn(tile[threadIdx.x][threadIdx.y]);
}

// ---------------- fp16 mma.sync GEMM, split into two K-halves --------------
#define BM 128
#define BN 128
#define BKE 32
#define ROWB 80
#define TILE_B (128 * ROWB)
#define STAGE_B (2 * TILE_B)
#define NSTAGE 4
#define NCHUNK_H 16                 // 512 / 32 per half
#define GEMM_SMEM (NSTAGE * STAGE_B)

__device__ __forceinline__ void load_stage(uint32_t sbase, int tid,
                                           int block_row, int block_col, int kt) {
#pragma unroll
    for (int l = 0; l < 4; l++) {
        int idx  = tid + l * 256;
        int tile = idx >> 9;             // 0:A 1:B
        int rem  = idx & 511;
        int r    = rem >> 2;
        int g    = rem & 3;
        uint32_t dstp = sbase + tile * TILE_B + r * ROWB + g * 16;
        const __half* src;
        int sz = 16;
        if (tile == 0) {
            int grow = block_row + r;
            if (grow >= N_NODES) { grow = N_NODES - 1; sz = 0; }
            src = g_A + (size_t)grow * KTOT + kt + g * 8;
        } else {
            src = g_Bt + (size_t)(block_col + r) * KTOT + kt + g * 8;
        }
        cp_async16(dstp, src, sz);
    }
}

__device__ __forceinline__ void gemm_mainloop(uint32_t sb0, int tid, int wid, int lane,
                                              int block_row, int block_col, int k_base,
                                              float (&acc)[2][8][4]) {
    const int m0w = (wid & 3) * 32;
    const int n0w = (wid >> 2) * 64;
#pragma unroll
    for (int s = 0; s < NSTAGE; s++) {
        load_stage(sb0 + s * STAGE_B, tid, block_row, block_col, k_base + s * BKE);
        CP_COMMIT();
    }
    const int arow    = lane & 15;
    const int acoloff = (lane >> 4) * 8;
    const int bq      = lane >> 3;
    const int brow    = ((bq >> 1) * 8) + (lane & 7);
    const int bkoff   = (bq & 1) * 8;

    for (int c = 0; c < NCHUNK_H; c++) {
        CP_WAIT3();
        __syncthreads();
        const uint32_t sb = sb0 + (c % NSTAGE) * STAGE_B;
#pragma unroll
        for (int ks = 0; ks < 2; ks++) {
            uint32_t a[2][4], b[8][2];
#pragma unroll
            for (int i = 0; i < 2; i++) {
                uint32_t ad = sb + (m0w + i * 16 + arow) * ROWB + (ks * 16 + acoloff) * 2;
                ldm_x4(a[i], ad);
            }
#pragma unroll
            for (int jj = 0; jj < 4; jj++) {
                uint32_t bd = sb + TILE_B + (n0w + jj * 16 + brow) * ROWB + (ks * 16 + bkoff) * 2;
                uint32_t r4[4];
                ldm_x4(r4, bd);
                b[jj*2][0] = r4[0]; b[jj*2][1] = r4[1];
                b[jj*2+1][0] = r4[2]; b[jj*2+1][1] = r4[3];
            }
#pragma unroll
            for (int i = 0; i < 2; i++)
#pragma unroll
                for (int j = 0; j < 8; j++)
                    mma_f16(acc[i][j], a[i], b[j]);
        }
        __syncthreads();
        if (c + NSTAGE < NCHUNK_H)
            load_stage(sb, tid, block_row, block_col, k_base + (c + NSTAGE) * BKE);
        CP_COMMIT();
    }
}

// GEMM1: out = x @ Wc  (K = 0..511), raw accumulator store
__global__ __launch_bounds__(256, 2)
void gemm1_kernel(float* __restrict__ out) {
    extern __shared__ char smem[];
    const uint32_t sb0 = smem_u32(smem);
    const int tid = threadIdx.x, wid = tid >> 5, lane = tid & 31;
    const int block_row = blockIdx.y * BM;
    const int block_col = blockIdx.x * BN;
    const int m0w = (wid & 3) * 32;
    const int n0w = (wid >> 2) * 64;

    float acc[2][8][4];
#pragma unroll
    for (int i = 0; i < 2; i++)
#pragma unroll
        for (int j = 0; j < 8; j++)
#pragma unroll
            for (int q = 0; q < 4; q++) acc[i][j][q] = 0.f;

    gemm_mainloop(sb0, tid, wid, lane, block_row, block_col, 0, acc);

#pragma unroll
    for (int i = 0; i < 2; i++) {
        int r0 = block_row + m0w + i * 16 + (lane >> 2);
        int r1 = r0 + 8;
        bool v0 = r0 < N_NODES, v1 = r1 < N_NODES;
#pragma unroll
        for (int j = 0; j < 8; j++) {
            int col = block_col + n0w + j * 8 + (lane & 3) * 2;
            if (v0) *reinterpret_cast<float2*>(out + (size_t)r0 * D + col)
                        = make_float2(acc[i][j][0], acc[i][j][1]);
            if (v1) *reinterpret_cast<float2*>(out + (size_t)r1 * D + col)
                        = make_float2(acc[i][j][2], acc[i][j][3]);
        }
    }
}

// GEMM2: out += (-mean) @ W2 + bc, deg-0 passthrough  (K = 512..1023)
__global__ __launch_bounds__(256, 2)
void gemm2_kernel(const float* __restrict__ x, float* __restrict__ out) {
    extern __shared__ char smem[];
    const uint32_t sb0 = smem_u32(smem);
    const int tid = threadIdx.x, wid = tid >> 5, lane = tid & 31;
    const int block_row = blockIdx.y * BM;
    const int block_col = blockIdx.x * BN;
    const int m0w = (wid & 3) * 32;
    const int n0w = (wid >> 2) * 64;

    float acc[2][8][4];
#pragma unroll
    for (int i = 0; i < 2; i++)
#pragma unroll
        for (int j = 0; j < 8; j++)
#pragma unroll
            for (int q = 0; q < 4; q++) acc[i][j][q] = 0.f;

    gemm_mainloop(sb0, tid, wid, lane, block_row, block_col, D, acc);

#pragma unroll
    for (int i = 0; i < 2; i++) {
        int r0 = block_row + m0w + i * 16 + (lane >> 2);
        int r1 = r0 + 8;
        bool v0 = r0 < N_NODES, v1 = r1 < N_NODES;
        int c0 = v0 ? g_deg[r0] : 0;
        int c1 = v1 ? g_deg[r1] : 0;
#pragma unroll
        for (int j = 0; j < 8; j++) {
            int col = block_col + n0w + j * 8 + (lane & 3) * 2;
            float b0 = g_bc[col], b1 = g_bc[col + 1];
            if (v0) {
                float2 o;
                if (c0 > 0) {
                    float2 p = *reinterpret_cast<const float2*>(out + (size_t)r0 * D + col);
                    o.x = p.x + acc[i][j][0] + b0;
                    o.y = p.y + acc[i][j][1] + b1;
                } else {
                    o = *reinterpret_cast<const float2*>(x + (size_t)r0 * D + col);
                }
                *reinterpret_cast<float2*>(out + (size_t)r0 * D + col) = o;
            }
            if (v1) {
                float2 o;
                if (c1 > 0) {
                    float2 p = *reinterpret_cast<const float2*>(out + (size_t)r1 * D + col);
                    o.x = p.x + acc[i][j][2] + b0;
                    o.y = p.y + acc[i][j][3] + b1;
                } else {
                    o = *reinterpret_cast<const float2*>(x + (size_t)r1 * D + col);
                }
                *reinterpret_cast<float2*>(out + (size_t)r1 * D + col) = o;
            }
        }
    }
}

// ---------------- launch ----------------
extern "C" void kernel_launch(void* const* d_in, const int* in_sizes, int n_in,
                              void* d_out, int out_size) {
    const float* x   = (const float*)d_in[0];
    const int*   src = (const int*)d_in[1];
    const int*   dst = (const int*)d_in[2];
    const float* W1  = (const float*)d_in[3];
    const float* b1  = (const float*)d_in[4];
    const float* W2  = (const float*)d_in[5];
    const float* b2  = (const float*)d_in[6];
    float* out = (float*)d_out;

    cudaFuncSetAttribute(gemm1_kernel, cudaFuncAttributeMaxDynamicSharedMemorySize, GEMM_SMEM);
    cudaFuncSetAttribute(gemm2_kernel, cudaFuncAttributeMaxDynamicSharedMemorySize, GEMM_SMEM);

    void *p_deg = nullptr, *p_cur = nullptr;
    cudaGetSymbolAddress(&p_deg, g_deg);
    cudaGetSymbolAddress(&p_cur, g_cursor);

    // fork a secondary stream for the x-dependent branch (bprep->xconv->GEMM1).
    // Created during capture and intentionally leaked (no device-memory alloc;
    // kernel_launch only runs during correctness + capture, never per-replay).
    cudaStream_t s1 = 0;
    bool forked = (cudaStreamCreateWithFlags(&s1, cudaStreamNonBlocking) == cudaSuccess);
    cudaEvent_t e0 = nullptr, e_x = nullptr, e_g1 = nullptr;
    if (forked) {
        forked = (cudaEventCreateWithFlags(&e0,  cudaEventDisableTiming) == cudaSuccess) &&
                 (cudaEventCreateWithFlags(&e_x, cudaEventDisableTiming) == cudaSuccess) &&
                 (cudaEventCreateWithFlags(&e_g1,cudaEventDisableTiming) == cudaSuccess);
        if (!forked) s1 = 0;
    }

    dim3 bg(KTOT / 32, D / 32), bb(32, 32);
    dim3 ggrid(D / BN, (N_NODES + BM - 1) / BM);

    // s0: zero deg/cursor
    cudaMemsetAsync(p_deg, 0, N_NODES * sizeof(int));
    cudaMemsetAsync(p_cur, 0, N_NODES * sizeof(int));

    if (forked) {
        cudaEventRecord(e0, 0);
        cudaStreamWaitEvent(s1, e0, 0);
    }

    // branch s1: bprep -> xconv -> GEMM1
    bprep_kernel<<<bg, bb, 0, s1>>>(W1, W2, b1, b2);
    xconv_kernel<<<XBLKS, 256, 0, s1>>>(x);
    if (forked) cudaEventRecord(e_x, s1);
    gemm1_kernel<<<ggrid, 256, GEMM_SMEM, s1>>>(out);
    if (forked) cudaEventRecord(e_g1, s1);

    // branch s0: hist -> scan -> fill -> agg
    hist_kernel<<<(N_EDGES + 255) / 256, 256>>>(dst);
    scan1_kernel<<<NSCAN_BLKS, 256>>>();
    scan2_kernel<<<1, 256>>>();
    scan3_kernel<<<NSCAN_BLKS, 256>>>();
    fill_kernel<<<(N_EDGES + 255) / 256, 256>>>(src, dst);
    if (forked) cudaStreamWaitEvent(0, e_x, 0);     // agg reads g_A[:,0:512]
    agg_kernel<<<N_NODES, 128>>>();

    // join: GEMM2 needs agg (s0), GEMM1 result + g_bc (s1)
    if (forked) cudaStreamWaitEvent(0, e_g1, 0);
    gemm2_kernel<<<ggrid, 256, GEMM_SMEM>>>(x, out);
}

// round 10
// speedup vs baseline: 1.1456x; 1.1456x over previous
#include <cuda_runtime.h>
#include <cuda_fp16.h>
#include <cstdint>

#define N_NODES 50000
#define D 512
#define N_EDGES 400000
#define KTOT 1024
#define XBLKS 25000          // xconv blocks: 50000*128 vec4 / 256
#define NSCAN_BLKS 196       // ceil(50000/256)

// ---------------- scratch (device globals: allocation-free) ----------------
__device__ __align__(16) int   g_deg[N_NODES];
__device__ __align__(16) int   g_off[N_NODES];
__device__ __align__(16) int   g_cursor[N_NODES];
__device__ __align__(16) int   g_bsum[256];
__device__ __align__(16) int   g_csr[N_EDGES];
__device__ __align__(16) float g_bc[D];
__device__ __align__(16) __half g_A[(size_t)N_NODES * KTOT];      // [x | -mean]
__device__ __align__(16) __half g_Bt[(size_t)D * KTOT];           // Bt[n][k]

// ---------------- asm helpers ----------------
__device__ __forceinline__ uint32_t smem_u32(const void* p) {
    uint32_t a;
    asm("{ .reg .u64 t; cvta.to.shared.u64 t, %1; cvt.u32.u64 %0, t; }" : "=r"(a) : "l"(p));
    return a;
}
__device__ __forceinline__ void cp_async16(uint32_t dst, const void* src, int sz) {
    asm volatile("cp.async.cg.shared.global [%0], [%1], 16, %2;"
                 :: "r"(dst), "l"(src), "r"(sz) : "memory");
}
#define CP_COMMIT() asm volatile("cp.async.commit_group;" ::: "memory")
#define CP_WAIT3()  asm volatile("cp.async.wait_group 3;" ::: "memory")

__device__ __forceinline__ void ldm_x4(uint32_t* d, uint32_t addr) {
    asm volatile("ldmatrix.sync.aligned.m8n8.x4.shared.b16 {%0,%1,%2,%3}, [%4];"
                 : "=r"(d[0]), "=r"(d[1]), "=r"(d[2]), "=r"(d[3]) : "r"(addr));
}
__device__ __forceinline__ void mma_f16(float* c, const uint32_t* a, const uint32_t* b) {
    asm volatile("mma.sync.aligned.m16n8k16.row.col.f32.f16.f16.f32 "
                 "{%0,%1,%2,%3}, {%4,%5,%6,%7}, {%8,%9}, {%0,%1,%2,%3};"
                 : "+f"(c[0]), "+f"(c[1]), "+f"(c[2]), "+f"(c[3])
                 : "r"(a[0]), "r"(a[1]), "r"(a[2]), "r"(a[3]), "r"(b[0]), "r"(b[1]));
}

// ---------------- xconv: g_A[:,0:512] = fp16(x) ----------------
__global__ void xconv_kernel(const float* __restrict__ x) {
    int idx = blockIdx.x * 256 + threadIdx.x;
    int row = idx >> 7;
    int c4  = (idx & 127) * 4;
    float4 v = *reinterpret_cast<const float4*>(x + (size_t)row * D + c4);
    __half2 h0 = __floats2half2_rn(v.x, v.y);
    __half2 h1 = __floats2half2_rn(v.z, v.w);
    uint2 w = make_uint2(*reinterpret_cast<uint32_t*>(&h0), *reinterpret_cast<uint32_t*>(&h1));
    *reinterpret_cast<uint2*>(g_A + (size_t)row * KTOT + c4) = w;
}

// ---------------- hist: 4 edges per thread via int4 ----------------
__global__ void hist_kernel(const int* __restrict__ dst) {
    int i = blockIdx.x * blockDim.x + threadIdx.x;   // over N_EDGES/4
    if (i < N_EDGES / 4) {
        int4 d4 = reinterpret_cast<const int4*>(dst)[i];
        atomicAdd(&g_deg[d4.x], 1);
        atomicAdd(&g_deg[d4.y], 1);
        atomicAdd(&g_deg[d4.z], 1);
        atomicAdd(&g_deg[d4.w], 1);
    }
}

// ---------------- multi-block exclusive scan ----------------
__global__ void scan1_kernel() {
    __shared__ int s[256];
    int t = threadIdx.x;
    int i = blockIdx.x * 256 + t;
    int v = (i < N_NODES) ? g_deg[i] : 0;
    s[t] = v;
    __syncthreads();
#pragma unroll
    for (int o = 1; o < 256; o <<= 1) {
        int tv = (t >= o) ? s[t - o] : 0;
        __syncthreads();
        s[t] += tv;
        __syncthreads();
    }
    if (i < N_NODES) g_off[i] = s[t] - v;
    if (t == 255) g_bsum[blockIdx.x] = s[255];
}
__global__ void scan2_kernel() {
    __shared__ int s[256];
    int t = threadIdx.x;
    int v = (t < NSCAN_BLKS) ? g_bsum[t] : 0;
    s[t] = v;
    __syncthreads();
#pragma unroll
    for (int o = 1; o < 256; o <<= 1) {
        int tv = (t >= o) ? s[t - o] : 0;
        __syncthreads();
        s[t] += tv;
        __syncthreads();
    }
    if (t < NSCAN_BLKS) g_bsum[t] = s[t] - v;
}
__global__ void scan3_kernel() {
    int t = threadIdx.x;
    int i = blockIdx.x * 256 + t;
    if (i < N_NODES) g_off[i] += g_bsum[blockIdx.x];
}

// ---------------- fill CSR ----------------
__global__ void fill_kernel(const int* __restrict__ src, const int* __restrict__ dst) {
    int e = blockIdx.x * blockDim.x + threadIdx.x;
    if (e >= N_EDGES) return;
    int d = dst[e];
    int p = g_off[d] + atomicAdd(&g_cursor[d], 1);
    g_csr[p] = src[e];
}

// ---------------- aggregate: g_A[:,512:1024] = fp16(-mean) -----------------
// CSR indices staged in smem first -> gather addresses known up-front (high MLP)
__global__ __launch_bounds__(128)
void agg_kernel() {
    __shared__ int sidx[128];
    int node = blockIdx.x;
    int t = threadIdx.x;
    int off = g_off[node];
    int deg = g_deg[node];

    float ax = 0.f, ay = 0.f, az = 0.f, aw = 0.f;
    for (int base = 0; base < deg; base += 128) {
        int cnt = min(128, deg - base);
        if (t < cnt) sidx[t] = g_csr[off + base + t];
        __syncthreads();
        int e = 0;
        for (; e + 2 <= cnt; e += 2) {
            const uint2* p0 = reinterpret_cast<const uint2*>(g_A + (size_t)sidx[e]     * KTOT + t * 4);
            const uint2* p1 = reinterpret_cast<const uint2*>(g_A + (size_t)sidx[e + 1] * KTOT + t * 4);
            uint2 w0 = *p0;
            uint2 w1 = *p1;
            float2 a0 = __half22float2(*reinterpret_cast<__half2*>(&w0.x));
            float2 a1 = __half22float2(*reinterpret_cast<__half2*>(&w0.y));
            float2 b0 = __half22float2(*reinterpret_cast<__half2*>(&w1.x));
            float2 b1 = __half22float2(*reinterpret_cast<__half2*>(&w1.y));
            ax += a0.x + b0.x; ay += a0.y + b0.y;
            az += a1.x + b1.x; aw += a1.y + b1.y;
        }
        if (e < cnt) {
            uint2 w0 = *reinterpret_cast<const uint2*>(g_A + (size_t)sidx[e] * KTOT + t * 4);
            float2 a0 = __half22float2(*reinterpret_cast<__half2*>(&w0.x));
            float2 a1 = __half22float2(*reinterpret_cast<__half2*>(&w0.y));
            ax += a0.x; ay += a0.y; az += a1.x; aw += a1.y;
        }
        __syncthreads();
    }
    float sc = (deg > 0) ? (-1.0f / (float)deg) : 0.f;
    __half2 m0 = __floats2half2_rn(ax * sc, ay * sc);
    __half2 m1 = __floats2half2_rn(az * sc, aw * sc);
    uint2 w = make_uint2(*reinterpret_cast<uint32_t*>(&m0), *reinterpret_cast<uint32_t*>(&m1));
    *reinterpret_cast<uint2*>(g_A + (size_t)node * KTOT + D + t * 4) = w;
}

// ---------------- bprep (+ bias): g_Bt = fp16(T([[W1+W2],[W2]])) -----------
__global__ void bprep_kernel(const float* __restrict__ W1, const float* __restrict__ W2,
                             const float* __restrict__ b1, const float* __restrict__ b2) {
    __shared__ float tile[32][33];
    if (blockIdx.x == 0 && blockIdx.y == 0) {
        int ft = threadIdx.y * 32 + threadIdx.x;
        if (ft < D) g_bc[ft] = b1[ft] + b2[ft];
    }
    int k0 = blockIdx.x * 32, n0 = blockIdx.y * 32;
    int kk = k0 + threadIdx.y, nn = n0 + threadIdx.x;
    float v = (kk < D) ? (W1[kk * D + nn] + W2[kk * D + nn]) : W2[(kk - D) * D + nn];
    tile[threadIdx.y][threadIdx.x] = v;
    __syncthreads();
    int wn = n0 + threadIdx.y, wk = k0 + threadIdx.x;
    g_Bt[(size_t)wn * KTOT + wk] = __float2half_rn(tile[threadIdx.x][threadIdx.y]);
}

// ---------------- fp16 mma.sync GEMM, single kernel (round-8 config) -------
#define BM 128
#define BN 128
#define BKE 32
#define ROWB 80
#define TILE_B (128 * ROWB)
#define STAGE_B (2 * TILE_B)
#define NSTAGE 4
#define NCHUNK (KTOT / BKE)
#define GEMM_SMEM (NSTAGE * STAGE_B)

__device__ __forceinline__ void load_stage(uint32_t sbase, int tid,
                                           int block_row, int block_col, int kt) {
#pragma unroll
    for (int l = 0; l < 4; l++) {
        int idx  = tid + l * 256;
        int tile = idx >> 9;             // 0:A 1:B
        int rem  = idx & 511;
        int r    = rem >> 2;
        int g    = rem & 3;
        uint32_t dstp = sbase + tile * TILE_B + r * ROWB + g * 16;
        const __half* src;
        int sz = 16;
        if (tile == 0) {
            int grow = block_row + r;
            if (grow >= N_NODES) { grow = N_NODES - 1; sz = 0; }
            src = g_A + (size_t)grow * KTOT + kt + g * 8;
        } else {
            src = g_Bt + (size_t)(block_col + r) * KTOT + kt + g * 8;
        }
        cp_async16(dstp, src, sz);
    }
}

__global__ __launch_bounds__(256, 2)
void gemm_mma_kernel(const float* __restrict__ x, float* __restrict__ out) {
    extern __shared__ char smem[];
    const uint32_t sb0 = smem_u32(smem);
    const int tid  = threadIdx.x;
    const int wid  = tid >> 5;
    const int lane = tid & 31;
    const int block_row = blockIdx.y * BM;
    const int block_col = blockIdx.x * BN;
    const int m0w = (wid & 3) * 32;
    const int n0w = (wid >> 2) * 64;

    float acc[2][8][4];
#pragma unroll
    for (int i = 0; i < 2; i++)
#pragma unroll
        for (int j = 0; j < 8; j++)
#pragma unroll
            for (int q = 0; q < 4; q++) acc[i][j][q] = 0.f;

#pragma unroll
    for (int s = 0; s < NSTAGE; s++) {
        load_stage(sb0 + s * STAGE_B, tid, block_row, block_col, s * BKE);
        CP_COMMIT();
    }

    const int arow    = lane & 15;
    const int acoloff = (lane >> 4) * 8;
    const int bq      = lane >> 3;
    const int brow    = ((bq >> 1) * 8) + (lane & 7);
    const int bkoff   = (bq & 1) * 8;

    for (int c = 0; c < NCHUNK; c++) {
        CP_WAIT3();
        __syncthreads();
        const uint32_t sb = sb0 + (c % NSTAGE) * STAGE_B;

#pragma unroll
        for (int ks = 0; ks < 2; ks++) {
            uint32_t a[2][4], b[8][2];
#pragma unroll
            for (int i = 0; i < 2; i++) {
                uint32_t ad = sb + (m0w + i * 16 + arow) * ROWB + (ks * 16 + acoloff) * 2;
                ldm_x4(a[i], ad);
            }
#pragma unroll
            for (int jj = 0; jj < 4; jj++) {
                uint32_t bd = sb + TILE_B + (n0w + jj * 16 + brow) * ROWB + (ks * 16 + bkoff) * 2;
                uint32_t r4[4];
                ldm_x4(r4, bd);
                b[jj*2][0] = r4[0]; b[jj*2][1] = r4[1];
                b[jj*2+1][0] = r4[2]; b[jj*2+1][1] = r4[3];
            }
#pragma unroll
            for (int i = 0; i < 2; i++)
#pragma unroll
                for (int j = 0; j < 8; j++)
                    mma_f16(acc[i][j], a[i], b[j]);
        }
        __syncthreads();
        if (c + NSTAGE < NCHUNK)
            load_stage(sb, tid, block_row, block_col, (c + NSTAGE) * BKE);
        CP_COMMIT();
    }

    // epilogue: bias + degree-0 passthrough
#pragma unroll
    for (int i = 0; i < 2; i++) {
        int r0 = block_row + m0w + i * 16 + (lane >> 2);
        int r1 = r0 + 8;
        bool v0 = r0 < N_NODES, v1 = r1 < N_NODES;
        int c0 = v0 ? g_deg[r0] : 0;
        int c1 = v1 ? g_deg[r1] : 0;
#pragma unroll
        for (int j = 0; j < 8; j++) {
            int col = block_col + n0w + j * 8 + (lane & 3) * 2;
            float b0 = g_bc[col], b1 = g_bc[col + 1];
            if (v0) {
                float2 o;
                if (c0 > 0) { o.x = acc[i][j][0] + b0; o.y = acc[i][j][1] + b1; }
                else { o = *reinterpret_cast<const float2*>(x + (size_t)r0 * D + col); }
                *reinterpret_cast<float2*>(out + (size_t)r0 * D + col) = o;
            }
            if (v1) {
                float2 o;
                if (c1 > 0) { o.x = acc[i][j][2] + b0; o.y = acc[i][j][3] + b1; }
                else { o = *reinterpret_cast<const float2*>(x + (size_t)r1 * D + col); }
                *reinterpret_cast<float2*>(out + (size_t)r1 * D + col) = o;
            }
        }
    }
}

// ---------------- launch ----------------
extern "C" void kernel_launch(void* const* d_in, const int* in_sizes, int n_in,
                              void* d_out, int out_size) {
    const float* x   = (const float*)d_in[0];
    const int*   src = (const int*)d_in[1];
    const int*   dst = (const int*)d_in[2];
    const float* W1  = (const float*)d_in[3];
    const float* b1  = (const float*)d_in[4];
    const float* W2  = (const float*)d_in[5];
    const float* b2  = (const float*)d_in[6];
    float* out = (float*)d_out;

    cudaFuncSetAttribute(gemm_mma_kernel, cudaFuncAttributeMaxDynamicSharedMemorySize, GEMM_SMEM);

    void *p_deg = nullptr, *p_cur = nullptr;
    cudaGetSymbolAddress(&p_deg, g_deg);
    cudaGetSymbolAddress(&p_cur, g_cursor);

    // fork a secondary stream only for the cheap prologue branch (bprep->xconv).
    // Created during capture and intentionally leaked (no device-memory alloc).
    cudaStream_t s1 = 0;
    bool forked = (cudaStreamCreateWithFlags(&s1, cudaStreamNonBlocking) == cudaSuccess);
    cudaEvent_t e0 = nullptr, e_x = nullptr;
    if (forked) {
        forked = (cudaEventCreateWithFlags(&e0,  cudaEventDisableTiming) == cudaSuccess) &&
                 (cudaEventCreateWithFlags(&e_x, cudaEventDisableTiming) == cudaSuccess);
        if (!forked) s1 = 0;
    }

    dim3 bg(KTOT / 32, D / 32), bb(32, 32);
    dim3 ggrid(D / BN, (N_NODES + BM - 1) / BM);

    cudaMemsetAsync(p_deg, 0, N_NODES * sizeof(int));
    cudaMemsetAsync(p_cur, 0, N_NODES * sizeof(int));

    if (forked) {
        cudaEventRecord(e0, 0);
        cudaStreamWaitEvent(s1, e0, 0);
    }

    // branch s1: bprep -> xconv (independent of CSR chain)
    bprep_kernel<<<bg, bb, 0, s1>>>(W1, W2, b1, b2);
    xconv_kernel<<<XBLKS, 256, 0, s1>>>(x);
    if (forked) cudaEventRecord(e_x, s1);

    // branch s0: hist -> scan -> fill
    hist_kernel<<<(N_EDGES / 4 + 255) / 256, 256>>>(dst);
    scan1_kernel<<<NSCAN_BLKS, 256>>>();
    scan2_kernel<<<1, 256>>>();
    scan3_kernel<<<NSCAN_BLKS, 256>>>();
    fill_kernel<<<(N_EDGES + 255) / 256, 256>>>(src, dst);

    // join: agg reads g_A[:,0:512] (xconv); gemm additionally needs g_Bt/g_bc (bprep)
    if (forked) cudaStreamWaitEvent(0, e_x, 0);
    agg_kernel<<<N_NODES, 128>>>();
    gemm_mma_kernel<<<ggrid, 256, GEMM_SMEM>>>(x, out);
}

// round 11
// speedup vs baseline: 1.2535x; 1.0942x over previous
#include <cuda_runtime.h>
#include <cuda_fp16.h>
#include <cstdint>

#define N_NODES 50000
#define D 512
#define N_EDGES 400000
#define KTOT 1024
#define XBLKS 25000          // xconv blocks: 50000*128 vec4 / 256
#define HBLKS 1563           // hist blocks: ceil(400000/256)
#define NSCAN_BLKS 196       // ceil(50000/256)

// ---------------- scratch (device globals: allocation-free) ----------------
__device__ __align__(16) int   g_deg[N_NODES];
__device__ __align__(16) int   g_off[N_NODES];
__device__ __align__(16) int   g_cursor[N_NODES];
__device__ __align__(16) int   g_bsum[256];
__device__ __align__(16) int   g_csr[N_EDGES];
__device__ __align__(16) float g_bc[D];
__device__ __align__(16) __half g_A[(size_t)N_NODES * KTOT];      // [x | -mean]
__device__ __align__(16) __half g_Bt[(size_t)D * KTOT];           // Bt[n][k]

// ---------------- asm helpers ----------------
__device__ __forceinline__ uint32_t smem_u32(const void* p) {
    uint32_t a;
    asm("{ .reg .u64 t; cvta.to.shared.u64 t, %1; cvt.u32.u64 %0, t; }" : "=r"(a) : "l"(p));
    return a;
}
__device__ __forceinline__ void cp_async16(uint32_t dst, const void* src, int sz) {
    asm volatile("cp.async.cg.shared.global [%0], [%1], 16, %2;"
                 :: "r"(dst), "l"(src), "r"(sz) : "memory");
}
#define CP_COMMIT() asm volatile("cp.async.commit_group;" ::: "memory")
#define CP_WAIT2()  asm volatile("cp.async.wait_group 2;" ::: "memory")

__device__ __forceinline__ void ldm_x4(uint32_t* d, uint32_t addr) {
    asm volatile("ldmatrix.sync.aligned.m8n8.x4.shared.b16 {%0,%1,%2,%3}, [%4];"
                 : "=r"(d[0]), "=r"(d[1]), "=r"(d[2]), "=r"(d[3]) : "r"(addr));
}
__device__ __forceinline__ void mma_f16(float* c, const uint32_t* a, const uint32_t* b) {
    asm volatile("mma.sync.aligned.m16n8k16.row.col.f32.f16.f16.f32 "
                 "{%0,%1,%2,%3}, {%4,%5,%6,%7}, {%8,%9}, {%0,%1,%2,%3};"
                 : "+f"(c[0]), "+f"(c[1]), "+f"(c[2]), "+f"(c[3])
                 : "r"(a[0]), "r"(a[1]), "r"(a[2]), "r"(a[3]), "r"(b[0]), "r"(b[1]));
}

// ---------------- 1. fused xconv + hist ----------------
__global__ void fused_hx_kernel(const float* __restrict__ x, const int* __restrict__ dst) {
    if (blockIdx.x < XBLKS) {
        int idx = blockIdx.x * 256 + threadIdx.x;      // vec4 group over x
        int row = idx >> 7;
        int c4  = (idx & 127) * 4;
        float4 v = *reinterpret_cast<const float4*>(x + (size_t)row * D + c4);
        __half2 h0 = __floats2half2_rn(v.x, v.y);
        __half2 h1 = __floats2half2_rn(v.z, v.w);
        uint2 w = make_uint2(*reinterpret_cast<uint32_t*>(&h0), *reinterpret_cast<uint32_t*>(&h1));
        *reinterpret_cast<uint2*>(g_A + (size_t)row * KTOT + c4) = w;
    } else {
        int e = (blockIdx.x - XBLKS) * 256 + threadIdx.x;
        if (e < N_EDGES) atomicAdd(&g_deg[dst[e]], 1);
    }
}

// ---------------- 2. multi-block exclusive scan: g_deg -> g_off ------------
__global__ void scan1_kernel() {
    __shared__ int s[256];
    int t = threadIdx.x;
    int i = blockIdx.x * 256 + t;
    int v = (i < N_NODES) ? g_deg[i] : 0;
    s[t] = v;
    __syncthreads();
#pragma unroll
    for (int o = 1; o < 256; o <<= 1) {
        int tv = (t >= o) ? s[t - o] : 0;
        __syncthreads();
        s[t] += tv;
        __syncthreads();
    }
    if (i < N_NODES) g_off[i] = s[t] - v;
    if (t == 255) g_bsum[blockIdx.x] = s[255];
}
__global__ void scan2_kernel() {
    __shared__ int s[256];
    int t = threadIdx.x;
    int v = (t < NSCAN_BLKS) ? g_bsum[t] : 0;
    s[t] = v;
    __syncthreads();
#pragma unroll
    for (int o = 1; o < 256; o <<= 1) {
        int tv = (t >= o) ? s[t - o] : 0;
        __syncthreads();
        s[t] += tv;
        __syncthreads();
    }
    if (t < NSCAN_BLKS) g_bsum[t] = s[t] - v;
}
__global__ void scan3_kernel() {
    int t = threadIdx.x;
    int i = blockIdx.x * 256 + t;
    if (i < N_NODES) g_off[i] += g_bsum[blockIdx.x];
}

// ---------------- 3. fill CSR ----------------
__global__ void fill_kernel(const int* __restrict__ src, const int* __restrict__ dst) {
    int e = blockIdx.x * blockDim.x + threadIdx.x;
    if (e >= N_EDGES) return;
    int d = dst[e];
    int p = g_off[d] + atomicAdd(&g_cursor[d], 1);
    g_csr[p] = src[e];
}

// ---------------- 4. aggregate: g_A[:,512:1024] = fp16(-mean) --------------
__global__ __launch_bounds__(128)
void agg_kernel() {
    int node = blockIdx.x;
    int t = threadIdx.x;
    int off = g_off[node];
    int deg = g_deg[node];

    float ax = 0.f, ay = 0.f, az = 0.f, aw = 0.f;
    for (int e = 0; e < deg; e++) {
        int s = g_csr[off + e];
        uint2 w = *reinterpret_cast<const uint2*>(g_A + (size_t)s * KTOT + t * 4);
        float2 f0 = __half22float2(*reinterpret_cast<__half2*>(&w.x));
        float2 f1 = __half22float2(*reinterpret_cast<__half2*>(&w.y));
        ax += f0.x; ay += f0.y; az += f1.x; aw += f1.y;
    }
    float sc = (deg > 0) ? (-1.0f / (float)deg) : 0.f;
    __half2 m0 = __floats2half2_rn(ax * sc, ay * sc);
    __half2 m1 = __floats2half2_rn(az * sc, aw * sc);
    uint2 w = make_uint2(*reinterpret_cast<uint32_t*>(&m0), *reinterpret_cast<uint32_t*>(&m1));
    *reinterpret_cast<uint2*>(g_A + (size_t)node * KTOT + D + t * 4) = w;
}

// ---------------- 5. bprep (+ bias): g_Bt = fp16(T([[W1+W2],[W2]])) --------
__global__ void bprep_kernel(const float* __restrict__ W1, const float* __restrict__ W2,
                             const float* __restrict__ b1, const float* __restrict__ b2) {
    __shared__ float tile[32][33];
    if (blockIdx.x == 0 && blockIdx.y == 0) {
        int ft = threadIdx.y * 32 + threadIdx.x;
        if (ft < D) g_bc[ft] = b1[ft] + b2[ft];
    }
    int k0 = blockIdx.x * 32, n0 = blockIdx.y * 32;
    int kk = k0 + threadIdx.y, nn = n0 + threadIdx.x;
    float v = (kk < D) ? (W1[kk * D + nn] + W2[kk * D + nn]) : W2[(kk - D) * D + nn];
    tile[threadIdx.y][threadIdx.x] = v;
    __syncthreads();
    int wn = n0 + threadIdx.y, wk = k0 + threadIdx.x;
    g_Bt[(size_t)wn * KTOT + wk] = __float2half_rn(tile[threadIdx.x][threadIdx.y]);
}

// ---------------- 6. fp16 mma.sync GEMM, single term, BKE=64 (r6 config) ---
#define BM 128
#define BN 128
#define BKE 64                      // fp16 K elems per chunk
#define ROWB 144                    // 128B data + 16B pad
#define TILE_B (128 * ROWB)         // 18432 B
#define STAGE_B (2 * TILE_B)        // 36864 B (A, B)
#define NSTAGE 3
#define NCHUNK (KTOT / BKE)         // 16
#define GEMM_SMEM (NSTAGE * STAGE_B)

__device__ __forceinline__ void load_stage(uint32_t sbase, int tid,
                                           int block_row, int block_col, int kt) {
#pragma unroll
    for (int l = 0; l < 8; l++) {
        int idx  = tid + l * 256;        // 0..2047
        int tile = idx >> 10;            // 0:A 1:B
        int rem  = idx & 1023;
        int r    = rem >> 3;             // row 0..127
        int g    = rem & 7;              // 16B granule (8 per 128B row)
        uint32_t dstp = sbase + tile * TILE_B + r * ROWB + g * 16;
        const __half* src;
        int sz = 16;
        if (tile == 0) {
            int grow = block_row + r;
            if (grow >= N_NODES) { grow = N_NODES - 1; sz = 0; }
            src = g_A + (size_t)grow * KTOT + kt + g * 8;
        } else {
            src = g_Bt + (size_t)(block_col + r) * KTOT + kt + g * 8;
        }
        cp_async16(dstp, src, sz);
    }
}

__global__ __launch_bounds__(256, 2)
void gemm_mma_kernel(const float* __restrict__ x, float* __restrict__ out) {
    extern __shared__ char smem[];
    const uint32_t sb0 = smem_u32(smem);
    const int tid  = threadIdx.x;
    const int wid  = tid >> 5;
    const int lane = tid & 31;
    const int block_row = blockIdx.y * BM;
    const int block_col = blockIdx.x * BN;
    const int m0w = (wid & 3) * 32;
    const int n0w = (wid >> 2) * 64;

    float acc[2][8][4];
#pragma unroll
    for (int i = 0; i < 2; i++)
#pragma unroll
        for (int j = 0; j < 8; j++)
#pragma unroll
            for (int q = 0; q < 4; q++) acc[i][j][q] = 0.f;

#pragma unroll
    for (int s = 0; s < NSTAGE; s++) {
        load_stage(sb0 + s * STAGE_B, tid, block_row, block_col, s * BKE);
        CP_COMMIT();
    }

    const int arow    = lane & 15;
    const int acoloff = (lane >> 4) * 8;
    const int bq      = lane >> 3;
    const int brow    = ((bq >> 1) * 8) + (lane & 7);
    const int bkoff   = (bq & 1) * 8;

    for (int c = 0; c < NCHUNK; c++) {
        CP_WAIT2();
        __syncthreads();
        const uint32_t sb = sb0 + (c % NSTAGE) * STAGE_B;

#pragma unroll
        for (int ks = 0; ks < 4; ks++) {
            uint32_t a[2][4], b[8][2];
#pragma unroll
            for (int i = 0; i < 2; i++) {
                uint32_t ad = sb + (m0w + i * 16 + arow) * ROWB + (ks * 16 + acoloff) * 2;
                ldm_x4(a[i], ad);
            }
#pragma unroll
            for (int jj = 0; jj < 4; jj++) {
                uint32_t bd = sb + TILE_B + (n0w + jj * 16 + brow) * ROWB + (ks * 16 + bkoff) * 2;
                uint32_t r4[4];
                ldm_x4(r4, bd);
                b[jj*2][0] = r4[0]; b[jj*2][1] = r4[1];
                b[jj*2+1][0] = r4[2]; b[jj*2+1][1] = r4[3];
            }
#pragma unroll
            for (int i = 0; i < 2; i++)
#pragma unroll
                for (int j = 0; j < 8; j++)
                    mma_f16(acc[i][j], a[i], b[j]);
        }
        __syncthreads();
        if (c + NSTAGE < NCHUNK)
            load_stage(sb, tid, block_row, block_col, (c + NSTAGE) * BKE);
        CP_COMMIT();
    }

    // epilogue: bias + degree-0 passthrough
#pragma unroll
    for (int i = 0; i < 2; i++) {
        int r0 = block_row + m0w + i * 16 + (lane >> 2);
        int r1 = r0 + 8;
        bool v0 = r0 < N_NODES, v1 = r1 < N_NODES;
        int c0 = v0 ? g_deg[r0] : 0;
        int c1 = v1 ? g_deg[r1] : 0;
#pragma unroll
        for (int j = 0; j < 8; j++) {
            int col = block_col + n0w + j * 8 + (lane & 3) * 2;
            float b0 = g_bc[col], b1 = g_bc[col + 1];
            if (v0) {
                float2 o;
                if (c0 > 0) { o.x = acc[i][j][0] + b0; o.y = acc[i][j][1] + b1; }
                else { o = *reinterpret_cast<const float2*>(x + (size_t)r0 * D + col); }
                *reinterpret_cast<float2*>(out + (size_t)r0 * D + col) = o;
            }
            if (v1) {
                float2 o;
                if (c1 > 0) { o.x = acc[i][j][2] + b0; o.y = acc[i][j][3] + b1; }
                else { o = *reinterpret_cast<const float2*>(x + (size_t)r1 * D + col); }
                *reinterpret_cast<float2*>(out + (size_t)r1 * D + col) = o;
            }
        }
    }
}

// ---------------- launch ----------------
extern "C" void kernel_launch(void* const* d_in, const int* in_sizes, int n_in,
                              void* d_out, int out_size) {
    const float* x   = (const float*)d_in[0];
    const int*   src = (const int*)d_in[1];
    const int*   dst = (const int*)d_in[2];
    const float* W1  = (const float*)d_in[3];
    const float* b1  = (const float*)d_in[4];
    const float* W2  = (const float*)d_in[5];
    const float* b2  = (const float*)d_in[6];
    float* out = (float*)d_out;

    cudaFuncSetAttribute(gemm_mma_kernel, cudaFuncAttributeMaxDynamicSharedMemorySize, GEMM_SMEM);

    void *p_deg = nullptr, *p_cur = nullptr;
    cudaGetSymbolAddress(&p_deg, g_deg);
    cudaGetSymbolAddress(&p_cur, g_cursor);
    cudaMemsetAsync(p_deg, 0, N_NODES * sizeof(int));
    cudaMemsetAsync(p_cur, 0, N_NODES * sizeof(int));

    fused_hx_kernel<<<XBLKS + HBLKS, 256>>>(x, dst);
    {
        dim3 bg(KTOT / 32, D / 32);
        dim3 bb(32, 32);
        bprep_kernel<<<bg, bb>>>(W1, W2, b1, b2);
    }
    scan1_kernel<<<NSCAN_BLKS, 256>>>();
    scan2_kernel<<<1, 256>>>();
    scan3_kernel<<<NSCAN_BLKS, 256>>>();
    fill_kernel<<<(N_EDGES + 255) / 256, 256>>>(src, dst);
    agg_kernel<<<N_NODES, 128>>>();
    {
        dim3 grid(D / BN, (N_NODES + BM - 1) / BM);
        gemm_mma_kernel<<<grid, 256, GEMM_SMEM>>>(x, out);
    }
}

// round 12
// speedup vs baseline: 1.2837x; 1.0241x over previous
#include <cuda_runtime.h>
#include <cuda_fp16.h>
#include <cstdint>

#define N_NODES 50000
#define D 512
#define N_EDGES 400000
#define KTOT 1024
#define XBLKS 25000          // xconv blocks: 50000*128 vec4 / 256
#define HBLKS 1563           // hist blocks: ceil(400000/256)
#define NSCAN_BLKS 196       // ceil(50000/256)

// ---------------- scratch (device globals: allocation-free) ----------------
__device__ __align__(16) int   g_deg[N_NODES];
__device__ __align__(16) int   g_off[N_NODES];
__device__ __align__(16) int   g_bsum[256];
__device__ __align__(16) int   g_rank[N_EDGES];
__device__ __align__(16) int   g_csr[N_EDGES];
__device__ __align__(16) float g_bc[D];
__device__ __align__(16) __half g_A[(size_t)N_NODES * KTOT];      // [x | -mean]
__device__ __align__(16) __half g_Bt[(size_t)D * KTOT];           // Bt[n][k]

// ---------------- asm helpers ----------------
__device__ __forceinline__ uint32_t smem_u32(const void* p) {
    uint32_t a;
    asm("{ .reg .u64 t; cvta.to.shared.u64 t, %1; cvt.u32.u64 %0, t; }" : "=r"(a) : "l"(p));
    return a;
}
__device__ __forceinline__ void cp_async16(uint32_t dst, const void* src, int sz) {
    asm volatile("cp.async.cg.shared.global [%0], [%1], 16, %2;"
                 :: "r"(dst), "l"(src), "r"(sz) : "memory");
}
#define CP_COMMIT() asm volatile("cp.async.commit_group;" ::: "memory")
#define CP_WAIT2()  asm volatile("cp.async.wait_group 2;" ::: "memory")

__device__ __forceinline__ void ldm_x4(uint32_t* d, uint32_t addr) {
    asm volatile("ldmatrix.sync.aligned.m8n8.x4.shared.b16 {%0,%1,%2,%3}, [%4];"
                 : "=r"(d[0]), "=r"(d[1]), "=r"(d[2]), "=r"(d[3]) : "r"(addr));
}
__device__ __forceinline__ void mma_f16(float* c, const uint32_t* a, const uint32_t* b) {
    asm volatile("mma.sync.aligned.m16n8k16.row.col.f32.f16.f16.f32 "
                 "{%0,%1,%2,%3}, {%4,%5,%6,%7}, {%8,%9}, {%0,%1,%2,%3};"
                 : "+f"(c[0]), "+f"(c[1]), "+f"(c[2]), "+f"(c[3])
                 : "r"(a[0]), "r"(a[1]), "r"(a[2]), "r"(a[3]), "r"(b[0]), "r"(b[1]));
}

// ---------------- 1. fused xconv + hist (hist records per-edge rank) -------
__global__ void fused_hx_kernel(const float* __restrict__ x, const int* __restrict__ dst) {
    if (blockIdx.x < XBLKS) {
        int idx = blockIdx.x * 256 + threadIdx.x;      // vec4 group over x
        int row = idx >> 7;
        int c4  = (idx & 127) * 4;
        float4 v = *reinterpret_cast<const float4*>(x + (size_t)row * D + c4);
        __half2 h0 = __floats2half2_rn(v.x, v.y);
        __half2 h1 = __floats2half2_rn(v.z, v.w);
        uint2 w = make_uint2(*reinterpret_cast<uint32_t*>(&h0), *reinterpret_cast<uint32_t*>(&h1));
        *reinterpret_cast<uint2*>(g_A + (size_t)row * KTOT + c4) = w;
    } else {
        int e = (blockIdx.x - XBLKS) * 256 + threadIdx.x;
        if (e < N_EDGES) g_rank[e] = atomicAdd(&g_deg[dst[e]], 1);
    }
}

// ---------------- 2. two-level exclusive scan: g_deg -> g_off, g_bsum ------
__global__ void scan1_kernel() {
    __shared__ int s[256];
    int t = threadIdx.x;
    int i = blockIdx.x * 256 + t;
    int v = (i < N_NODES) ? g_deg[i] : 0;
    s[t] = v;
    __syncthreads();
#pragma unroll
    for (int o = 1; o < 256; o <<= 1) {
        int tv = (t >= o) ? s[t - o] : 0;
        __syncthreads();
        s[t] += tv;
        __syncthreads();
    }
    if (i < N_NODES) g_off[i] = s[t] - v;
    if (t == 255) g_bsum[blockIdx.x] = s[255];
}
__global__ void scan2_kernel() {
    __shared__ int s[256];
    int t = threadIdx.x;
    int v = (t < NSCAN_BLKS) ? g_bsum[t] : 0;
    s[t] = v;
    __syncthreads();
#pragma unroll
    for (int o = 1; o < 256; o <<= 1) {
        int tv = (t >= o) ? s[t - o] : 0;
        __syncthreads();
        s[t] += tv;
        __syncthreads();
    }
    if (t < NSCAN_BLKS) g_bsum[t] = s[t] - v;
}

// ---------------- 3. fill CSR (atomic-free: rank + two-level offset) -------
__global__ void fill_kernel(const int* __restrict__ src, const int* __restrict__ dst) {
    int e = blockIdx.x * blockDim.x + threadIdx.x;
    if (e >= N_EDGES) return;
    int d = dst[e];
    int p = g_off[d] + g_bsum[d >> 8] + g_rank[e];
    g_csr[p] = src[e];
}

// ---------------- 4. aggregate: g_A[:,512:1024] = fp16(-mean) --------------
__global__ __launch_bounds__(128)
void agg_kernel() {
    int node = blockIdx.x;
    int t = threadIdx.x;
    int off = g_off[node] + g_bsum[node >> 8];
    int deg = g_deg[node];

    float ax = 0.f, ay = 0.f, az = 0.f, aw = 0.f;
    for (int e = 0; e < deg; e++) {
        int s = g_csr[off + e];
        uint2 w = *reinterpret_cast<const uint2*>(g_A + (size_t)s * KTOT + t * 4);
        float2 f0 = __half22float2(*reinterpret_cast<__half2*>(&w.x));
        float2 f1 = __half22float2(*reinterpret_cast<__half2*>(&w.y));
        ax += f0.x; ay += f0.y; az += f1.x; aw += f1.y;
    }
    float sc = (deg > 0) ? (-1.0f / (float)deg) : 0.f;
    __half2 m0 = __floats2half2_rn(ax * sc, ay * sc);
    __half2 m1 = __floats2half2_rn(az * sc, aw * sc);
    uint2 w = make_uint2(*reinterpret_cast<uint32_t*>(&m0), *reinterpret_cast<uint32_t*>(&m1));
    *reinterpret_cast<uint2*>(g_A + (size_t)node * KTOT + D + t * 4) = w;
}

// ---------------- 5. bprep (+ bias): g_Bt = fp16(T([[W1+W2],[W2]])) --------
__global__ void bprep_kernel(const float* __restrict__ W1, const float* __restrict__ W2,
                             const float* __restrict__ b1, const float* __restrict__ b2) {
    __shared__ float tile[32][33];
    if (blockIdx.x == 0 && blockIdx.y == 0) {
        int ft = threadIdx.y * 32 + threadIdx.x;
        if (ft < D) g_bc[ft] = b1[ft] + b2[ft];
    }
    int k0 = blockIdx.x * 32, n0 = blockIdx.y * 32;
    int kk = k0 + threadIdx.y, nn = n0 + threadIdx.x;
    float v = (kk < D) ? (W1[kk * D + nn] + W2[kk * D + nn]) : W2[(kk - D) * D + nn];
    tile[threadIdx.y][threadIdx.x] = v;
    __syncthreads();
    int wn = n0 + threadIdx.y, wk = k0 + threadIdx.x;
    g_Bt[(size_t)wn * KTOT + wk] = __float2half_rn(tile[threadIdx.x][threadIdx.y]);
}

// ---------------- 6. fp16 mma.sync GEMM, single term, BKE=64 ---------------
#define BM 128
#define BN 128
#define BKE 64                      // fp16 K elems per chunk
#define ROWB 144                    // 128B data + 16B pad
#define TILE_B (128 * ROWB)         // 18432 B
#define STAGE_B (2 * TILE_B)        // 36864 B (A, B)
#define NSTAGE 3
#define NCHUNK (KTOT / BKE)         // 16
#define GEMM_SMEM (NSTAGE * STAGE_B)

__device__ __forceinline__ void load_stage(uint32_t sbase, int tid,
                                           int block_row, int block_col, int kt) {
#pragma unroll
    for (int l = 0; l < 8; l++) {
        int idx  = tid + l * 256;        // 0..2047
        int tile = idx >> 10;            // 0:A 1:B
        int rem  = idx & 1023;
        int r    = rem >> 3;             // row 0..127
        int g    = rem & 7;              // 16B granule (8 per 128B row)
        uint32_t dstp = sbase + tile * TILE_B + r * ROWB + g * 16;
        const __half* src;
        int sz = 16;
        if (tile == 0) {
            int grow = block_row + r;
            if (grow >= N_NODES) { grow = N_NODES - 1; sz = 0; }
            src = g_A + (size_t)grow * KTOT + kt + g * 8;
        } else {
            src = g_Bt + (size_t)(block_col + r) * KTOT + kt + g * 8;
        }
        cp_async16(dstp, src, sz);
    }
}

__global__ __launch_bounds__(256, 2)
void gemm_mma_kernel(const float* __restrict__ x, float* __restrict__ out) {
    extern __shared__ char smem[];
    const uint32_t sb0 = smem_u32(smem);
    const int tid  = threadIdx.x;
    const int wid  = tid >> 5;
    const int lane = tid & 31;
    const int block_row = blockIdx.y * BM;
    const int block_col = blockIdx.x * BN;
    const int m0w = (wid & 3) * 32;
    const int n0w = (wid >> 2) * 64;

    float acc[2][8][4];
#pragma unroll
    for (int i = 0; i < 2; i++)
#pragma unroll
        for (int j = 0; j < 8; j++)
#pragma unroll
            for (int q = 0; q < 4; q++) acc[i][j][q] = 0.f;

#pragma unroll
    for (int s = 0; s < NSTAGE; s++) {
        load_stage(sb0 + s * STAGE_B, tid, block_row, block_col, s * BKE);
        CP_COMMIT();
    }

    const int arow    = lane & 15;
    const int acoloff = (lane >> 4) * 8;
    const int bq      = lane >> 3;
    const int brow    = ((bq >> 1) * 8) + (lane & 7);
    const int bkoff   = (bq & 1) * 8;

    for (int c = 0; c < NCHUNK; c++) {
        CP_WAIT2();
        __syncthreads();
        const uint32_t sb = sb0 + (c % NSTAGE) * STAGE_B;

#pragma unroll
        for (int ks = 0; ks < 4; ks++) {
            uint32_t a[2][4], b[8][2];
#pragma unroll
            for (int i = 0; i < 2; i++) {
                uint32_t ad = sb + (m0w + i * 16 + arow) * ROWB + (ks * 16 + acoloff) * 2;
                ldm_x4(a[i], ad);
            }
#pragma unroll
            for (int jj = 0; jj < 4; jj++) {
                uint32_t bd = sb + TILE_B + (n0w + jj * 16 + brow) * ROWB + (ks * 16 + bkoff) * 2;
                uint32_t r4[4];
                ldm_x4(r4, bd);
                b[jj*2][0] = r4[0]; b[jj*2][1] = r4[1];
                b[jj*2+1][0] = r4[2]; b[jj*2+1][1] = r4[3];
            }
#pragma unroll
            for (int i = 0; i < 2; i++)
#pragma unroll
                for (int j = 0; j < 8; j++)
                    mma_f16(acc[i][j], a[i], b[j]);
        }
        __syncthreads();
        if (c + NSTAGE < NCHUNK)
            load_stage(sb, tid, block_row, block_col, (c + NSTAGE) * BKE);
        CP_COMMIT();
    }

    // epilogue: bias + degree-0 passthrough
#pragma unroll
    for (int i = 0; i < 2; i++) {
        int r0 = block_row + m0w + i * 16 + (lane >> 2);
        int r1 = r0 + 8;
        bool v0 = r0 < N_NODES, v1 = r1 < N_NODES;
        int c0 = v0 ? g_deg[r0] : 0;
        int c1 = v1 ? g_deg[r1] : 0;
#pragma unroll
        for (int j = 0; j < 8; j++) {
            int col = block_col + n0w + j * 8 + (lane & 3) * 2;
            float b0 = g_bc[col], b1 = g_bc[col + 1];
            if (v0) {
                float2 o;
                if (c0 > 0) { o.x = acc[i][j][0] + b0; o.y = acc[i][j][1] + b1; }
                else { o = *reinterpret_cast<const float2*>(x + (size_t)r0 * D + col); }
                *reinterpret_cast<float2*>(out + (size_t)r0 * D + col) = o;
            }
            if (v1) {
                float2 o;
                if (c1 > 0) { o.x = acc[i][j][2] + b0; o.y = acc[i][j][3] + b1; }
                else { o = *reinterpret_cast<const float2*>(x + (size_t)r1 * D + col); }
                *reinterpret_cast<float2*>(out + (size_t)r1 * D + col) = o;
            }
        }
    }
}

// ---------------- launch ----------------
extern "C" void kernel_launch(void* const* d_in, const int* in_sizes, int n_in,
                              void* d_out, int out_size) {
    const float* x   = (const float*)d_in[0];
    const int*   src = (const int*)d_in[1];
    const int*   dst = (const int*)d_in[2];
    const float* W1  = (const float*)d_in[3];
    const float* b1  = (const float*)d_in[4];
    const float* W2  = (const float*)d_in[5];
    const float* b2  = (const float*)d_in[6];
    float* out = (float*)d_out;

    cudaFuncSetAttribute(gemm_mma_kernel, cudaFuncAttributeMaxDynamicSharedMemorySize, GEMM_SMEM);

    void *p_deg = nullptr;
    cudaGetSymbolAddress(&p_deg, g_deg);
    cudaMemsetAsync(p_deg, 0, N_NODES * sizeof(int));

    fused_hx_kernel<<<XBLKS + HBLKS, 256>>>(x, dst);
    {
        dim3 bg(KTOT / 32, D / 32);
        dim3 bb(32, 32);
        bprep_kernel<<<bg, bb>>>(W1, W2, b1, b2);
    }
    scan1_kernel<<<NSCAN_BLKS, 256>>>();
    scan2_kernel<<<1, 256>>>();
    fill_kernel<<<(N_EDGES + 255) / 256, 256>>>(src, dst);
    agg_kernel<<<N_NODES, 128>>>();
    {
        dim3 grid(D / BN, (N_NODES + BM - 1) / BM);
        gemm_mma_kernel<<<grid, 256, GEMM_SMEM>>>(x, out);
    }
}